// round 4
// baseline (speedup 1.0000x reference)
#include <cuda_runtime.h>
#include <cstdint>

#define BB 128
#define SS 32768
#define PP 65536
#define POS_W 5.0f

static_assert((PP % 256) == 0, "blocks must not span batches");

// Scratch (allocation-free rule: __device__ globals)
__device__ __align__(16) unsigned char g_gt[(size_t)BB * SS];  // 4 MiB
__device__ double g_acc;
__device__ int g_paths_is64;

// ---------------------------------------------------------------------------
// Kernel A: detect paths dtype. Values are < 2^15, so an int64 layout has
// every odd 32-bit word == 0. OR the odd words of the first 2048 words:
// zero => int64, nonzero => int32. (For int32, odd words are sorted pj
// values — cannot all be zero.)
// ---------------------------------------------------------------------------
__global__ void detect_kernel(const unsigned* __restrict__ pw) {
    unsigned v = 0;
    for (int i = (int)threadIdx.x * 2 + 1; i < 2048; i += 64)
        v |= pw[i];
#pragma unroll
    for (int o = 16; o > 0; o >>= 1)
        v |= __shfl_xor_sync(0xFFFFFFFFu, v, o);
    if (threadIdx.x == 0) g_paths_is64 = (v == 0u) ? 1 : 0;
}

// ---------------------------------------------------------------------------
// Kernel 0: zero the gt bitmap (uint4 stores) and the accumulator.
// ---------------------------------------------------------------------------
__global__ void zero_kernel() {
    unsigned i = blockIdx.x * blockDim.x + threadIdx.x;
    ((uint4*)g_gt)[i] = make_uint4(0u, 0u, 0u, 0u);
    if (i == 0) g_acc = 0.0;
}

// ---------------------------------------------------------------------------
// Kernel 1: scatter. One thread per path entry (B*P = 8,388,608).
// pj sorted per batch => is_first == (k==0 || pj[k] != pj[k-1]).
// hit = is_first && targets[b][pj]==1  =>  gt[b][pi] = 1 (plain store; every
// effective writer stores 1, so the race is benign).
// Branch on dtype flag is uniform across the whole grid.
// ---------------------------------------------------------------------------
__global__ void scatter_kernel(const void* __restrict__ paths_v,
                               const int* __restrict__ targets) {
    unsigned idx = blockIdx.x * blockDim.x + threadIdx.x;   // < 2^23
    unsigned k = idx & (PP - 1);   // step within batch
    unsigned b = idx >> 16;        // P = 2^16

    int pi, pj, prev;
    if (g_paths_is64) {
        const long long* paths = (const long long*)paths_v;
        longlong2 pp = ((const longlong2*)paths)[idx];      // 16B coalesced
        pi = (int)pp.x; pj = (int)pp.y;
        prev = __shfl_up_sync(0xFFFFFFFFu, pj, 1);
        if ((threadIdx.x & 31) == 0)
            prev = (k == 0) ? -1 : (int)paths[(size_t)idx * 2 - 1];
    } else {
        const int* paths = (const int*)paths_v;
        int2 pp = ((const int2*)paths)[idx];                // 8B coalesced
        pi = pp.x; pj = pp.y;
        prev = __shfl_up_sync(0xFFFFFFFFu, pj, 1);
        if ((threadIdx.x & 31) == 0)
            prev = (k == 0) ? -1 : paths[(size_t)idx * 2 - 1];
    }

    if (pj != prev) {                                   // is_first
        if (targets[b * SS + pj] == 1) {                // gather, row L2-resident
            g_gt[b * SS + pi] = (unsigned char)1;
        }
    }
}

// ---------------------------------------------------------------------------
// Kernel 2: loss + reduction. 4 elements per thread (float4 preds, 4 gt bytes).
// loss = 5*gt*softplus(-x) + (1-gt)*softplus(x);
// softplus(x) = max(x,0) + log1p(exp(-|x|)).
// ---------------------------------------------------------------------------
__global__ void loss_kernel(const float* __restrict__ preds) {
    unsigned i = blockIdx.x * blockDim.x + threadIdx.x;   // < B*S/4
    float4 p = ((const float4*)preds)[i];
    unsigned g4 = ((const unsigned*)g_gt)[i];

    float sum = 0.0f;
    float xv[4] = {p.x, p.y, p.z, p.w};
#pragma unroll
    for (int j = 0; j < 4; ++j) {
        float x = xv[j];
        bool gt = ((g4 >> (8 * j)) & 0xFFu) != 0u;
        float shared_t = log1pf(__expf(-fabsf(x)));
        float l = gt ? POS_W * (fmaxf(-x, 0.0f) + shared_t)
                     : (fmaxf(x, 0.0f) + shared_t);
        sum += l;
    }

    // warp reduce
#pragma unroll
    for (int off = 16; off > 0; off >>= 1)
        sum += __shfl_xor_sync(0xFFFFFFFFu, sum, off);

    __shared__ float ws[8];
    int w = threadIdx.x >> 5;
    if ((threadIdx.x & 31) == 0) ws[w] = sum;
    __syncthreads();
    if (threadIdx.x < 8) {
        float v = ws[threadIdx.x];
#pragma unroll
        for (int off = 4; off > 0; off >>= 1)
            v += __shfl_xor_sync(0xFFu, v, off);
        if (threadIdx.x == 0)
            atomicAdd(&g_acc, (double)v);
    }
}

// ---------------------------------------------------------------------------
// Kernel 3: finalize. mean over B*S, write float32 scalar.
// ---------------------------------------------------------------------------
__global__ void finalize_kernel(float* __restrict__ out) {
    out[0] = (float)(g_acc * (1.0 / ((double)BB * (double)SS)));
}

extern "C" void kernel_launch(void* const* d_in, const int* in_sizes, int n_in,
                              void* d_out, int out_size) {
    // Robust input binding: `paths` is uniquely the largest input
    // (B*P*2 = 16,777,216 elements vs B*S = 4,194,304 for preds/targets).
    // Among the remaining two, preds precedes targets in both dict order
    // (preds, targets, paths) and alphabetical order (paths, preds, targets).
    int pi_idx = 0;
    for (int i = 1; i < n_in; ++i)
        if (in_sizes[i] > in_sizes[pi_idx]) pi_idx = i;

    const void* paths = d_in[pi_idx];
    const float* preds = nullptr;
    const int*   targets = nullptr;
    for (int i = 0; i < n_in; ++i) {
        if (i == pi_idx) continue;
        if (!preds) preds = (const float*)d_in[i];
        else        targets = (const int*)d_in[i];
    }

    float* out = (float*)d_out;

    detect_kernel<<<1, 32>>>((const unsigned*)paths);
    zero_kernel<<<1024, 256>>>();                         // 262144 threads, 16B each
    scatter_kernel<<<(BB * PP) / 256, 256>>>(paths, targets);
    loss_kernel<<<(BB * SS) / (4 * 256), 256>>>(preds);
    finalize_kernel<<<1, 1>>>(out);
}

// round 6
// speedup vs baseline: 1.6865x; 1.6865x over previous
#include <cuda_runtime.h>
#include <cstdint>

#define BB 128
#define SS 32768
#define PP 65536
#define POS_W 5.0f

static_assert((PP % 512) == 0, "blocks must not span batches");

// Scratch (allocation-free rule: __device__ globals)
__device__ __align__(16) unsigned char g_gt[(size_t)BB * SS];  // 4 MiB
__device__ double g_acc;
__device__ unsigned g_done;
__device__ int g_paths_is64;

// ---------------------------------------------------------------------------
// Kernel 0: zero gt bitmap (uint4 stores), reset accumulators, and detect
// paths dtype (block 0, warp 0). Values < 2^15, so an int64 layout has every
// odd 32-bit word == 0; int32 layout has odd words = sorted pj (nonzero OR).
// ---------------------------------------------------------------------------
__global__ void zero_kernel(const unsigned* __restrict__ pw) {
    unsigned i = blockIdx.x * blockDim.x + threadIdx.x;
    ((uint4*)g_gt)[i] = make_uint4(0u, 0u, 0u, 0u);
    if (i == 0) { g_acc = 0.0; g_done = 0u; }
    if (blockIdx.x == 0 && threadIdx.x < 32) {
        unsigned v = 0;
        for (int j = (int)threadIdx.x * 2 + 1; j < 2048; j += 64)
            v |= pw[j];
#pragma unroll
        for (int o = 16; o > 0; o >>= 1)
            v |= __shfl_xor_sync(0xFFFFFFFFu, v, o);
        if (threadIdx.x == 0) g_paths_is64 = (v == 0u) ? 1 : 0;
    }
}

// ---------------------------------------------------------------------------
// Kernel 1: scatter. TWO path entries per thread (B*P/2 = 4,194,304 threads).
// pj sorted per batch => is_first == (k==0 || pj[k] != pj[k-1]).
// Entry 2t's prev comes from the lane neighbor's second pj (shuffle); entry
// 2t+1's prev is in-register. Lane 0 loads the single straggler scalar.
// All effective gt writers store 1 => plain byte store, benign race.
// Paths are streamed with __ldcs (evict-first) to keep targets/gt in L2.
// ---------------------------------------------------------------------------
__global__ void scatter_kernel(const void* __restrict__ paths_v,
                               const int* __restrict__ targets) {
    unsigned t = blockIdx.x * blockDim.x + threadIdx.x;   // < B*P/2 = 2^22
    unsigned k0 = (t & (PP / 2 - 1)) * 2;   // first entry's step within batch
    unsigned b  = t >> 15;                  // P/2 = 2^15 threads per batch

    int pi0, pj0, pi1, pj1, prev0;
    if (g_paths_is64) {
        const uint4* p = (const uint4*)paths_v;           // 1 entry per uint4
        uint4 v0 = __ldcs(p + (size_t)2 * t);
        uint4 v1 = __ldcs(p + (size_t)2 * t + 1);
        pi0 = (int)v0.x; pj0 = (int)v0.z;                 // low words (LE)
        pi1 = (int)v1.x; pj1 = (int)v1.z;
        prev0 = __shfl_up_sync(0xFFFFFFFFu, pj1, 1);
        if ((threadIdx.x & 31) == 0)
            prev0 = (k0 == 0) ? -1
                  : (int)((const long long*)paths_v)[(size_t)4 * t - 1];
    } else {
        const int4* p = (const int4*)paths_v;             // 2 entries per int4
        int4 v = __ldcs(p + t);
        pi0 = v.x; pj0 = v.y; pi1 = v.z; pj1 = v.w;
        prev0 = __shfl_up_sync(0xFFFFFFFFu, pj1, 1);
        if ((threadIdx.x & 31) == 0)
            prev0 = (k0 == 0) ? -1
                  : ((const int*)paths_v)[(size_t)4 * t - 1];
    }

    const int* trow = targets + b * SS;
    unsigned char* grow = g_gt + b * SS;
    if (pj0 != prev0 && trow[pj0] == 1) grow[pi0] = (unsigned char)1;
    if (pj1 != pj0   && trow[pj1] == 1) grow[pi1] = (unsigned char)1;
}

// ---------------------------------------------------------------------------
// Kernel 2: loss + reduction + finalize. 8 elements per thread
// (2x float4 preds, 8 gt bytes). loss = 5*gt*softplus(-x)+(1-gt)*softplus(x);
// softplus(x) = max(x,0) + log(1 + exp(-|x|)), fast-math MUFU versions
// (arg of log in [1,2] -> abs err ~1e-7, negligible vs 1e-3 threshold).
// Last finished block writes the mean to out.
// ---------------------------------------------------------------------------
__global__ void loss_kernel(const float* __restrict__ preds,
                            float* __restrict__ out) {
    unsigned i = blockIdx.x * blockDim.x + threadIdx.x;   // < B*S/8
    float4 p0 = ((const float4*)preds)[(size_t)2 * i];
    float4 p1 = ((const float4*)preds)[(size_t)2 * i + 1];
    uint2 g = ((const uint2*)g_gt)[i];

    float xv[8] = {p0.x, p0.y, p0.z, p0.w, p1.x, p1.y, p1.z, p1.w};
    unsigned gb[8];
#pragma unroll
    for (int j = 0; j < 4; ++j) { gb[j] = (g.x >> (8 * j)) & 0xFFu; }
#pragma unroll
    for (int j = 0; j < 4; ++j) { gb[4 + j] = (g.y >> (8 * j)) & 0xFFu; }

    float sum = 0.0f;
#pragma unroll
    for (int j = 0; j < 8; ++j) {
        float x = xv[j];
        float t = __logf(1.0f + __expf(-fabsf(x)));
        float l = gb[j] ? POS_W * (fmaxf(-x, 0.0f) + t)
                        : (fmaxf(x, 0.0f) + t);
        sum += l;
    }

    // warp reduce
#pragma unroll
    for (int off = 16; off > 0; off >>= 1)
        sum += __shfl_xor_sync(0xFFFFFFFFu, sum, off);

    __shared__ float ws[8];
    int w = threadIdx.x >> 5;
    if ((threadIdx.x & 31) == 0) ws[w] = sum;
    __syncthreads();
    if (threadIdx.x == 0) {
        float v = 0.0f;
#pragma unroll
        for (int j = 0; j < 8; ++j) v += ws[j];
        atomicAdd(&g_acc, (double)v);
        __threadfence();
        unsigned done = atomicAdd(&g_done, 1u);
        if (done == gridDim.x - 1) {
            // All other blocks' g_acc adds are ordered before their g_done
            // increments (threadfence); our atomic observed the final count,
            // so a volatile read sees the complete sum.
            double s = *((volatile double*)&g_acc);
            out[0] = (float)(s * (1.0 / ((double)BB * (double)SS)));
        }
    }
}

extern "C" void kernel_launch(void* const* d_in, const int* in_sizes, int n_in,
                              void* d_out, int out_size) {
    // paths is uniquely the largest input (B*P*2 elements). Among the rest,
    // preds precedes targets in both dict and alphabetical orderings.
    int pi_idx = 0;
    for (int i = 1; i < n_in; ++i)
        if (in_sizes[i] > in_sizes[pi_idx]) pi_idx = i;

    const void* paths = d_in[pi_idx];
    const float* preds = nullptr;
    const int*   targets = nullptr;
    for (int i = 0; i < n_in; ++i) {
        if (i == pi_idx) continue;
        if (!preds) preds = (const float*)d_in[i];
        else        targets = (const int*)d_in[i];
    }
    float* out = (float*)d_out;

    zero_kernel<<<1024, 256>>>((const unsigned*)paths);           // 4 MiB clear
    scatter_kernel<<<(BB * PP / 2) / 256, 256>>>(paths, targets); // 2 entries/thr
    loss_kernel<<<(BB * SS / 8) / 256, 256>>>(preds, out);        // 8 elems/thr
}